// round 2
// baseline (speedup 1.0000x reference)
#include <cuda_runtime.h>
#include <math.h>

#define T_LEN 512
#define B_SZ  64
#define D_SZ  1024
#define H_SZ  512
#define L_SZ  5

#define NCTA 128
#define NTHR 256

// ---------------- scratch (device globals: no allocation allowed) ----------------
__device__ float g_XHt[T_LEN * H_SZ * B_SZ];   // [t][j][b]  x@W_H + b_H  (64 MB)
__device__ float g_XCt[T_LEN * H_SZ * B_SZ];   // [t][j][b]  x@W_C + b_C  (64 MB)
__device__ float g_h[2][H_SZ * B_SZ];          // hidden double buffer, [j][b]
__device__ float g_part[2][4][H_SZ][B_SZ];     // K-split partials: [gate][kg][j][b]
__device__ unsigned g_cnt = 0;                 // monotonic arrival counter
__device__ unsigned g_gen = 0;                 // monotonic generation (release)

// ---------------- grid-wide barrier (persistent kernel, 128 co-resident CTAs) ----
// Monotonic ticket/generation: no reset needed, safe across graph replays,
// wrap-safe via signed difference.
__device__ __forceinline__ void gbar() {
    __syncthreads();
    if (threadIdx.x == 0) {
        __threadfence();                               // release prior writes
        unsigned ticket = atomicAdd(&g_cnt, 1u);
        unsigned phase  = ticket >> 7;                 // / NCTA (128)
        unsigned target = phase + 1u;
        if ((ticket & (NCTA - 1)) == (NCTA - 1)) {
            atomicExch(&g_gen, target);                // last arrival releases
        } else {
            while ((int)(*(volatile unsigned*)&g_gen - target) < 0) { }
        }
        __threadfence();                               // acquire
    }
    __syncthreads();
}

// ---------------- precompute: XHt/XCt[t][j][b] = x[t,b,:]@W[:,j] + bias[j] -------
// M=32768 (t*64+b), K=1024, N=512. 128x64 CTA tile, BK=32, 8x4 per thread.
__global__ void __launch_bounds__(NTHR) proj_kernel(
    const float* __restrict__ x,
    const float* __restrict__ Ww,
    const float* __restrict__ Wb,
    const int gate)
{
    __shared__ float As[32][128];   // [k][m]
    __shared__ float Bs[32][64];    // [k][j]
    float* __restrict__ dst = gate ? g_XCt : g_XHt;

    const int tid = threadIdx.x;
    const int bm  = blockIdx.x * 128;
    const int bn  = blockIdx.y * 64;
    const int tm  = tid & 15;
    const int tn  = tid >> 4;

    float acc[8][4];
#pragma unroll
    for (int i = 0; i < 8; i++)
#pragma unroll
        for (int j = 0; j < 4; j++) acc[i][j] = 0.0f;

    for (int k0 = 0; k0 < D_SZ; k0 += 32) {
        // stage A tile: 128 rows x 32 k  (coalesced float4 along k, transpose via STS)
#pragma unroll
        for (int r = 0; r < 4; r++) {
            int lin = tid + r * 256;          // 0..1023 float4 units
            int m = lin >> 3, kq = lin & 7;
            float4 v = *(const float4*)(x + (size_t)(bm + m) * D_SZ + k0 + kq * 4);
            As[kq * 4 + 0][m] = v.x;
            As[kq * 4 + 1][m] = v.y;
            As[kq * 4 + 2][m] = v.z;
            As[kq * 4 + 3][m] = v.w;
        }
        // stage B tile: 32 rows x 64 j
#pragma unroll
        for (int r = 0; r < 2; r++) {
            int lin = tid + r * 256;          // 0..511 float4 units
            int kk = lin >> 4, jq = lin & 15;
            *(float4*)&Bs[kk][jq * 4] =
                *(const float4*)(Ww + (size_t)(k0 + kk) * H_SZ + bn + jq * 4);
        }
        __syncthreads();
#pragma unroll
        for (int k = 0; k < 32; k++) {
            float4 a0 = *(const float4*)&As[k][tm * 4];
            float4 a1 = *(const float4*)&As[k][64 + tm * 4];
            float4 bv = *(const float4*)&Bs[k][tn * 4];
            float av[8] = {a0.x, a0.y, a0.z, a0.w, a1.x, a1.y, a1.z, a1.w};
            float bw[4] = {bv.x, bv.y, bv.z, bv.w};
#pragma unroll
            for (int i = 0; i < 8; i++)
#pragma unroll
                for (int j = 0; j < 4; j++)
                    acc[i][j] = fmaf(av[i], bw[j], acc[i][j]);
        }
        __syncthreads();
    }

#pragma unroll
    for (int i = 0; i < 8; i++) {
        int m = bm + ((i < 4) ? (tm * 4 + i) : (64 + tm * 4 + i - 4));
        int t = m >> 6, b = m & 63;
#pragma unroll
        for (int j = 0; j < 4; j++) {
            int jj = bn + tn * 4 + j;
            dst[(size_t)t * (H_SZ * B_SZ) + (size_t)jj * B_SZ + b] = acc[i][j] + Wb[jj];
        }
    }
}

// ---------------- persistent sequential kernel: 2 passes x 512 t x 5 layers ------
// Phase A: 128 CTAs = 32 j-groups x 4 k-groups; CTA tile = 64b x 16j x 128k per gate.
//          Thread = 4 consecutive b x 1 j x 2 gates (8 fp32 accumulators).
// Phase B: 1 hidden element per thread: reduce 4 partials, bias (+X proj at l==0),
//          tanh/sigmoid highway combine, write next hidden (+ outputs at l==L-1).
__global__ void __launch_bounds__(NTHR, 1) rhn_seq_kernel(
    const float* __restrict__ RHw, const float* __restrict__ RHb,
    const float* __restrict__ RCw, const float* __restrict__ RCb,
    float* __restrict__ out)
{
    const int tid = threadIdx.x;
    const int cta = blockIdx.x;

    __shared__ float hs[32][64];      // [k][b] chunk of hidden
    __shared__ float rhs_s[32][16];   // [k][j] chunk of R_H
    __shared__ float rcs_s[32][16];   // [k][j] chunk of R_C

    // h0 = 0
    g_h[0][cta * NTHR + tid] = 0.0f;
    gbar();

    const int jx  = tid & 15;         // j within 16-wide group
    const int byq = tid >> 4;         // b quad index (4 consecutive b)
    const int jg  = cta & 31;
    const int kg  = cta >> 5;
    const int j0  = jg * 16;
    const int k0  = kg * 128;

    const int e   = cta * NTHR + tid; // phase-B element (0..32767)
    const int eb  = e & 63;
    const int ej  = e >> 6;

    int p = 0;
    for (int pass = 0; pass < 2; pass++)
    for (int t = 0; t < T_LEN; t++)
    for (int l = 0; l < L_SZ; l++) {
        const float* __restrict__ Rh = RHw + (size_t)l * H_SZ * H_SZ;
        const float* __restrict__ Rc = RCw + (size_t)l * H_SZ * H_SZ;
        const float* __restrict__ hp = g_h[p];

        float aH0 = 0, aH1 = 0, aH2 = 0, aH3 = 0;
        float aC0 = 0, aC1 = 0, aC2 = 0, aC3 = 0;

        const int kk_r = tid >> 3, jq_r = tid & 7;

        // software-pipelined staging: prefetch chunk 0
        float4 h0v, h1v;
        float2 r0v, r1v;
        {
            const float4* h4 = (const float4*)(hp + k0 * 64);
            h0v = h4[tid];
            h1v = h4[tid + 256];
            r0v = *(const float2*)(Rh + (size_t)(k0 + kk_r) * H_SZ + j0 + 2 * jq_r);
            r1v = *(const float2*)(Rc + (size_t)(k0 + kk_r) * H_SZ + j0 + 2 * jq_r);
        }
#pragma unroll
        for (int c = 0; c < 4; c++) {
            __syncthreads();
            ((float4*)hs)[tid]       = h0v;
            ((float4*)hs)[tid + 256] = h1v;
            ((float2*)rhs_s)[tid]    = r0v;
            ((float2*)rcs_s)[tid]    = r1v;
            __syncthreads();
            if (c < 3) {
                int kb = k0 + (c + 1) * 32;
                const float4* h4 = (const float4*)(hp + kb * 64);
                h0v = h4[tid];
                h1v = h4[tid + 256];
                r0v = *(const float2*)(Rh + (size_t)(kb + kk_r) * H_SZ + j0 + 2 * jq_r);
                r1v = *(const float2*)(Rc + (size_t)(kb + kk_r) * H_SZ + j0 + 2 * jq_r);
            }
#pragma unroll
            for (int kk = 0; kk < 32; kk++) {
                float rh = rhs_s[kk][jx];
                float rc = rcs_s[kk][jx];
                float4 hv = *(const float4*)&hs[kk][byq * 4];
                aH0 = fmaf(hv.x, rh, aH0); aH1 = fmaf(hv.y, rh, aH1);
                aH2 = fmaf(hv.z, rh, aH2); aH3 = fmaf(hv.w, rh, aH3);
                aC0 = fmaf(hv.x, rc, aC0); aC1 = fmaf(hv.y, rc, aC1);
                aC2 = fmaf(hv.z, rc, aC2); aC3 = fmaf(hv.w, rc, aC3);
            }
        }
        *(float4*)&g_part[0][kg][j0 + jx][byq * 4] = make_float4(aH0, aH1, aH2, aH3);
        *(float4*)&g_part[1][kg][j0 + jx][byq * 4] = make_float4(aC0, aC1, aC2, aC3);
        gbar();

        // ---- phase B: reduce + activations + highway combine ----
        {
            float sH = g_part[0][0][ej][eb] + g_part[0][1][ej][eb]
                     + g_part[0][2][ej][eb] + g_part[0][3][ej][eb];
            float sC = g_part[1][0][ej][eb] + g_part[1][1][ej][eb]
                     + g_part[1][2][ej][eb] + g_part[1][3][ej][eb];
            sH += RHb[l * H_SZ + ej];
            sC += RCb[l * H_SZ + ej];
            if (l == 0) {
                sH += g_XHt[(size_t)t * (H_SZ * B_SZ) + e];
                sC += g_XCt[(size_t)t * (H_SZ * B_SZ) + e];
            }
            float hold = g_h[p][e];
            float hl = tanhf(sH);
            float tl = 1.0f / (1.0f + expf(-sC));
            float hn = hl * tl + hold * (1.0f - tl);
            g_h[p ^ 1][e] = hn;
            if (l == L_SZ - 1) {
                size_t o = (size_t)t * (B_SZ * 2 * H_SZ) + (size_t)eb * (2 * H_SZ)
                         + (size_t)pass * H_SZ + ej;
                out[o] = hn;
                if (t == T_LEN - 1) {
                    out[(size_t)T_LEN * (B_SZ * 2 * H_SZ) + (size_t)eb * (2 * H_SZ)
                        + (size_t)pass * H_SZ + ej] = hn;
                }
            }
        }
        gbar();
        p ^= 1;
    }
}

extern "C" void kernel_launch(void* const* d_in, const int* in_sizes, int n_in,
                              void* d_out, int out_size)
{
    const float* x   = (const float*)d_in[0];
    const float* WHw = (const float*)d_in[1];
    const float* WHb = (const float*)d_in[2];
    const float* WCw = (const float*)d_in[3];
    const float* WCb = (const float*)d_in[4];
    const float* RHw = (const float*)d_in[5];
    const float* RHb = (const float*)d_in[6];
    const float* RCw = (const float*)d_in[7];
    const float* RCb = (const float*)d_in[8];
    float* out = (float*)d_out;

    dim3 pg(256, 8);
    proj_kernel<<<pg, NTHR>>>(x, WHw, WHb, 0);
    proj_kernel<<<pg, NTHR>>>(x, WCw, WCb, 1);
    rhn_seq_kernel<<<NCTA, NTHR>>>(RHw, RHb, RCw, RCb, out);
}